// round 1
// baseline (speedup 1.0000x reference)
#include <cuda_runtime.h>
#include <math.h>

static constexpr int DIM = 2048;
static constexpr float NSC_A = 3.4445f;
static constexpr float NSC_B = -4.7750f;
static constexpr float NSC_C = 2.0315f;

// Scratch (allocation-free rule: __device__ globals)
__device__ float g_X[DIM * DIM];
__device__ float g_X2[DIM * DIM];
__device__ float g_G[DIM * DIM];   // Gram = X X^T
__device__ float g_Bm[DIM * DIM];  // B = b*G + c*G@G
__device__ float g_partial[256];
__device__ float g_scale;

// ---------------- Frobenius norm (deterministic 2-pass) ----------------
__global__ void norm_partial_kernel(const float* __restrict__ w, int n) {
    __shared__ float sdata[256];
    float s = 0.f;
    for (int i = blockIdx.x * blockDim.x + threadIdx.x; i < n;
         i += gridDim.x * blockDim.x) {
        float v = w[i];
        s = fmaf(v, v, s);
    }
    sdata[threadIdx.x] = s;
    __syncthreads();
    for (int o = 128; o; o >>= 1) {
        if (threadIdx.x < o) sdata[threadIdx.x] += sdata[threadIdx.x + o];
        __syncthreads();
    }
    if (threadIdx.x == 0) g_partial[blockIdx.x] = sdata[0];
}

__global__ void norm_finalize_kernel() {
    __shared__ float sdata[256];
    sdata[threadIdx.x] = g_partial[threadIdx.x];
    __syncthreads();
    for (int o = 128; o; o >>= 1) {
        if (threadIdx.x < o) sdata[threadIdx.x] += sdata[threadIdx.x + o];
        __syncthreads();
    }
    if (threadIdx.x == 0) g_scale = 1.0f / (sqrtf(sdata[0]) + 1e-7f);
}

__global__ void scale_kernel(const float* __restrict__ w, float* __restrict__ X, int n) {
    const float s = g_scale;
    for (int i = blockIdx.x * blockDim.x + threadIdx.x; i < n;
         i += gridDim.x * blockDim.x) {
        X[i] = w[i] * s;
    }
}

// ---------------- SGEMM: 128x128 tile, BK=8, 8x8/thread, double-buffered ----
// MODE 0: C = A @ op(B)
// MODE 1: C = NSC_C * (A@B) + NSC_B * Aux      (Aux = full MxN matrix)
// MODE 2: C = (A@B) + NSC_A * Aux              (Aux = full MxN matrix)
// MODE 3: C = (A@B) + Aux[col]                 (Aux = bias, length N)
template <int MODE, bool TRANSB>
__global__ __launch_bounds__(256, 2) void gemm128(
    int M, int N, int K,
    const float* __restrict__ A,
    const float* __restrict__ B,
    const float* __restrict__ Aux,
    float* __restrict__ C) {
    __shared__ float As[2][8][128];
    __shared__ float Bs[2][8][128];

    const int tid = threadIdx.x;
    const int tx = tid & 15;   // N-dir 0..15
    const int ty = tid >> 4;   // M-dir 0..15
    const int bN = blockIdx.x * 128;
    const int bM = blockIdx.y * 128;

    // A-tile load map: 128 rows x 8 cols as float4 along K
    const int lrow = tid >> 1;        // 0..127
    const int lk4 = (tid & 1) * 4;    // 0 or 4
    // B-tile load map (NN): 8 rows x 128 cols as float4 along N
    const int bkrow = tid >> 5;       // 0..7
    const int bcol4 = (tid & 31) * 4; // 0..124

    const float* Ap = A + (size_t)(bM + lrow) * K + lk4;
    const float* Bp;
    if (TRANSB)
        Bp = B + (size_t)(bN + lrow) * K + lk4;
    else
        Bp = B + (size_t)bkrow * N + (bN + bcol4);

    float acc[8][8];
#pragma unroll
    for (int i = 0; i < 8; i++)
#pragma unroll
        for (int j = 0; j < 8; j++) acc[i][j] = 0.f;

    // preload first tile
    float4 av = *(const float4*)Ap;
    float4 bv = *(const float4*)Bp;

    As[0][lk4 + 0][lrow] = av.x;
    As[0][lk4 + 1][lrow] = av.y;
    As[0][lk4 + 2][lrow] = av.z;
    As[0][lk4 + 3][lrow] = av.w;
    if (TRANSB) {
        Bs[0][lk4 + 0][lrow] = bv.x;
        Bs[0][lk4 + 1][lrow] = bv.y;
        Bs[0][lk4 + 2][lrow] = bv.z;
        Bs[0][lk4 + 3][lrow] = bv.w;
    } else {
        *(float4*)&Bs[0][bkrow][bcol4] = bv;
    }
    __syncthreads();

    int buf = 0;
    for (int k0 = 0; k0 < K; k0 += 8) {
        const bool has_next = (k0 + 8) < K;
        if (has_next) {
            av = *(const float4*)(Ap + (k0 + 8));
            if (TRANSB)
                bv = *(const float4*)(Bp + (k0 + 8));
            else
                bv = *(const float4*)(Bp + (size_t)(k0 + 8) * N);
        }

#pragma unroll
        for (int kk = 0; kk < 8; kk++) {
            float a0[8], b0[8];
            float4 t;
            t = *(const float4*)&As[buf][kk][ty * 4];
            a0[0] = t.x; a0[1] = t.y; a0[2] = t.z; a0[3] = t.w;
            t = *(const float4*)&As[buf][kk][64 + ty * 4];
            a0[4] = t.x; a0[5] = t.y; a0[6] = t.z; a0[7] = t.w;
            t = *(const float4*)&Bs[buf][kk][tx * 4];
            b0[0] = t.x; b0[1] = t.y; b0[2] = t.z; b0[3] = t.w;
            t = *(const float4*)&Bs[buf][kk][64 + tx * 4];
            b0[4] = t.x; b0[5] = t.y; b0[6] = t.z; b0[7] = t.w;
#pragma unroll
            for (int i = 0; i < 8; i++)
#pragma unroll
                for (int j = 0; j < 8; j++) acc[i][j] = fmaf(a0[i], b0[j], acc[i][j]);
        }

        if (has_next) {
            const int nb = buf ^ 1;
            As[nb][lk4 + 0][lrow] = av.x;
            As[nb][lk4 + 1][lrow] = av.y;
            As[nb][lk4 + 2][lrow] = av.z;
            As[nb][lk4 + 3][lrow] = av.w;
            if (TRANSB) {
                Bs[nb][lk4 + 0][lrow] = bv.x;
                Bs[nb][lk4 + 1][lrow] = bv.y;
                Bs[nb][lk4 + 2][lrow] = bv.z;
                Bs[nb][lk4 + 3][lrow] = bv.w;
            } else {
                *(float4*)&Bs[nb][bkrow][bcol4] = bv;
            }
            __syncthreads();
            buf = nb;
        }
    }

    // epilogue: four 4x4 quadrant sub-tiles
#pragma unroll
    for (int ib = 0; ib < 2; ib++) {
#pragma unroll
        for (int i = 0; i < 4; i++) {
            const int r = bM + ib * 64 + ty * 4 + i;
            float* Crow = C + (size_t)r * N;
            const float* AuxRow = (MODE == 1 || MODE == 2) ? (Aux + (size_t)r * N) : Aux;
#pragma unroll
            for (int jb = 0; jb < 2; jb++) {
                const int c = bN + jb * 64 + tx * 4;
                const int ai = ib * 4 + i;
                float4 v;
                v.x = acc[ai][jb * 4 + 0];
                v.y = acc[ai][jb * 4 + 1];
                v.z = acc[ai][jb * 4 + 2];
                v.w = acc[ai][jb * 4 + 3];
                if (MODE == 1) {
                    float4 ax = *(const float4*)&AuxRow[c];
                    v.x = NSC_C * v.x + NSC_B * ax.x;
                    v.y = NSC_C * v.y + NSC_B * ax.y;
                    v.z = NSC_C * v.z + NSC_B * ax.z;
                    v.w = NSC_C * v.w + NSC_B * ax.w;
                } else if (MODE == 2) {
                    float4 ax = *(const float4*)&AuxRow[c];
                    v.x = fmaf(NSC_A, ax.x, v.x);
                    v.y = fmaf(NSC_A, ax.y, v.y);
                    v.z = fmaf(NSC_A, ax.z, v.z);
                    v.w = fmaf(NSC_A, ax.w, v.w);
                } else if (MODE == 3) {
                    float4 bb = *(const float4*)&Aux[c];
                    v.x += bb.x; v.y += bb.y; v.z += bb.z; v.w += bb.w;
                }
                *(float4*)&Crow[c] = v;
            }
        }
    }
}

// ---------------- launch ----------------
extern "C" void kernel_launch(void* const* d_in, const int* in_sizes, int n_in,
                              void* d_out, int out_size) {
    // Identify inputs by size (x: B*DIM, w: DIM*DIM, b: DIM)
    const float* x = nullptr;
    const float* w = nullptr;
    const float* bias = nullptr;
    int x_size = 0;
    for (int i = 0; i < n_in; i++) {
        const int sz = in_sizes[i];
        if (sz == DIM) bias = (const float*)d_in[i];
        else if (sz == DIM * DIM) w = (const float*)d_in[i];
        else { x = (const float*)d_in[i]; x_size = sz; }
    }
    const int B_rows = x_size / DIM;  // 16384
    float* out = (float*)d_out;

    float *pX, *pX2, *pG, *pB;
    cudaGetSymbolAddress((void**)&pX, g_X);
    cudaGetSymbolAddress((void**)&pX2, g_X2);
    cudaGetSymbolAddress((void**)&pG, g_G);
    cudaGetSymbolAddress((void**)&pB, g_Bm);

    const int n = DIM * DIM;
    norm_partial_kernel<<<256, 256>>>(w, n);
    norm_finalize_kernel<<<1, 256>>>();
    scale_kernel<<<1024, 256>>>(w, pX, n);

    dim3 blk(256);
    dim3 g16(DIM / 128, DIM / 128);
    for (int s = 0; s < 10; s++) {
        float* Xin = (s & 1) ? pX2 : pX;
        float* Xout = (s & 1) ? pX : pX2;
        // Gram = Xin @ Xin^T
        gemm128<0, true><<<g16, blk>>>(DIM, DIM, DIM, Xin, Xin, pX, pG);
        // Bm = NSC_C * (Gram @ Gram) + NSC_B * Gram
        gemm128<1, false><<<g16, blk>>>(DIM, DIM, DIM, pG, pG, pG, pB);
        // Xout = (Bm @ Xin) + NSC_A * Xin
        gemm128<2, false><<<g16, blk>>>(DIM, DIM, DIM, pB, Xin, Xin, Xout);
    }
    // out = x @ X_final + bias   (after 10 steps, final X is in pX)
    dim3 gout(DIM / 128, B_rows / 128);
    gemm128<3, false><<<gout, blk>>>(B_rows, DIM, DIM, x, pX, bias, out);
}

// round 3
// speedup vs baseline: 1.9845x; 1.9845x over previous
#include <cuda_runtime.h>
#include <cuda_bf16.h>
#include <cstdint>
#include <math.h>

static constexpr int DIM = 2048;
static constexpr int LD = 2048;
static constexpr float NSC_A = 3.4445f;
static constexpr float NSC_B = -4.7750f;
static constexpr float NSC_C = 2.0315f;

// ---------------- scratch (allocation-free: __device__ globals) -------------
__device__ __align__(256) float g_X [DIM * DIM];
__device__ __align__(256) float g_X2[DIM * DIM];
__device__ __align__(256) float g_G [DIM * DIM];
__device__ __align__(256) __nv_bfloat16 g_Xhi [DIM * DIM];
__device__ __align__(256) __nv_bfloat16 g_Xlo [DIM * DIM];
__device__ __align__(256) __nv_bfloat16 g_XThi[DIM * DIM];
__device__ __align__(256) __nv_bfloat16 g_XTlo[DIM * DIM];
__device__ __align__(256) __nv_bfloat16 g_Ghi [DIM * DIM];
__device__ __align__(256) __nv_bfloat16 g_Glo [DIM * DIM];
__device__ __align__(256) __nv_bfloat16 g_Bhi [DIM * DIM];
__device__ __align__(256) __nv_bfloat16 g_Blo [DIM * DIM];
__device__ __align__(256) __nv_bfloat16 g_xbig_hi[16384 * DIM];
__device__ __align__(256) __nv_bfloat16 g_xbig_lo[16384 * DIM];
__device__ float g_partial[256];
__device__ float g_scale;

// ---------------- helpers ----------------------------------------------------
__device__ __forceinline__ uint32_t smem_u32(const void* p) {
    uint32_t a;
    asm("{ .reg .u64 t; cvta.to.shared.u64 t, %1; cvt.u32.u64 %0, t; }" : "=r"(a) : "l"(p));
    return a;
}
__device__ __forceinline__ void cpa16(uint32_t dst, const void* src) {
    asm volatile("cp.async.cg.shared.global [%0], [%1], 16;" :: "r"(dst), "l"(src) : "memory");
}
#define CP_COMMIT() asm volatile("cp.async.commit_group;" ::: "memory")
#define CP_WAIT1()  asm volatile("cp.async.wait_group 1;" ::: "memory")

#define LDMX4(r, a)                                                              \
    asm volatile("ldmatrix.sync.aligned.m8n8.x4.shared.b16 {%0,%1,%2,%3}, [%4];" \
        : "=r"((r)[0]), "=r"((r)[1]), "=r"((r)[2]), "=r"((r)[3]) : "r"(a))

#define MMA16816(acc, a, b0, b1)                                                  \
    asm volatile("mma.sync.aligned.m16n8k16.row.col.f32.bf16.bf16.f32 "           \
        "{%0,%1,%2,%3}, {%4,%5,%6,%7}, {%8,%9}, {%0,%1,%2,%3};"                   \
        : "+f"((acc)[0]), "+f"((acc)[1]), "+f"((acc)[2]), "+f"((acc)[3])          \
        : "r"((a)[0]), "r"((a)[1]), "r"((a)[2]), "r"((a)[3]), "r"(b0), "r"(b1))

// ---------------- small kernels ---------------------------------------------
__global__ void norm_partial_kernel(const float* __restrict__ w, int n) {
    __shared__ float sd[256];
    float s = 0.f;
    for (int i = blockIdx.x * blockDim.x + threadIdx.x; i < n; i += gridDim.x * blockDim.x) {
        float v = w[i];
        s = fmaf(v, v, s);
    }
    sd[threadIdx.x] = s;
    __syncthreads();
    for (int o = 128; o; o >>= 1) {
        if (threadIdx.x < o) sd[threadIdx.x] += sd[threadIdx.x + o];
        __syncthreads();
    }
    if (threadIdx.x == 0) g_partial[blockIdx.x] = sd[0];
}
__global__ void norm_finalize_kernel() {
    __shared__ float sd[256];
    sd[threadIdx.x] = g_partial[threadIdx.x];
    __syncthreads();
    for (int o = 128; o; o >>= 1) {
        if (threadIdx.x < o) sd[threadIdx.x] += sd[threadIdx.x + o];
        __syncthreads();
    }
    if (threadIdx.x == 0) g_scale = 1.0f / (sqrtf(sd[0]) + 1e-7f);
}
// scale + split in one pass
__global__ void scale_split_kernel(const float* __restrict__ w, float* __restrict__ X,
                                   __nv_bfloat16* __restrict__ hi, __nv_bfloat16* __restrict__ lo,
                                   int n) {
    const float s = g_scale;
    for (int i = blockIdx.x * blockDim.x + threadIdx.x; i < n; i += gridDim.x * blockDim.x) {
        float v = w[i] * s;
        X[i] = v;
        __nv_bfloat16 h = __float2bfloat16(v);
        hi[i] = h;
        lo[i] = __float2bfloat16(v - __bfloat162float(h));
    }
}
__global__ void split_kernel(const float* __restrict__ s, __nv_bfloat16* __restrict__ hi,
                             __nv_bfloat16* __restrict__ lo, int n) {
    for (int i = blockIdx.x * blockDim.x + threadIdx.x; i < n; i += gridDim.x * blockDim.x) {
        float v = s[i];
        __nv_bfloat16 h = __float2bfloat16(v);
        hi[i] = h;
        lo[i] = __float2bfloat16(v - __bfloat162float(h));
    }
}
// transposed split: dst[r][c] = src[c][r], hi/lo bf16
__global__ void strans_kernel(const float* __restrict__ src,
                              __nv_bfloat16* __restrict__ dhi, __nv_bfloat16* __restrict__ dlo) {
    __shared__ float t[32][33];
    int x = blockIdx.x * 32 + threadIdx.x;
    int y0 = blockIdx.y * 32;
    for (int j = threadIdx.y; j < 32; j += 8)
        t[j][threadIdx.x] = src[(size_t)(y0 + j) * LD + x];
    __syncthreads();
    int ox = blockIdx.y * 32 + threadIdx.x;
    for (int j = threadIdx.y; j < 32; j += 8) {
        float v = t[threadIdx.x][j];
        size_t o = (size_t)(blockIdx.x * 32 + j) * LD + ox;
        __nv_bfloat16 h = __float2bfloat16(v);
        dhi[o] = h;
        dlo[o] = __float2bfloat16(v - __bfloat162float(h));
    }
}

// ---------------- split-bf16 GEMM via mma.sync (sm_100-safe) -----------------
// C[m,n] = sum_k A[m,k]*B[n,k]; both operands K-major bf16 hi/lo pairs.
// acc = Ahi@Bhi + Ahi@Blo + Alo@Bhi  (fp32 accumulate)
// MODE 0: v = acc                       MODE 1: v = NSC_C*acc + NSC_B*aux[m,n]
// MODE 2: v = acc + NSC_A*aux[m,n]      MODE 3: v = acc + aux[n] (bias)
static constexpr int BM = 128, BN = 128, BKE = 64;
static constexpr int NCH = DIM / BKE;            // 32 k-chunks
static constexpr int TILE_B = BM * 128;          // 16 KB (128 rows x 128B)
static constexpr int STAGE_B = 4 * TILE_B;       // Ahi|Alo|Bhi|Blo = 64 KB
static constexpr int STAGES = 3;
static constexpr int SMEM_TOTAL = STAGES * STAGE_B;  // 192 KB

template <int MODE, bool WF32, bool WSPLIT>
__global__ __launch_bounds__(256, 1) void mmagemm(
    const __nv_bfloat16* __restrict__ Ahi, const __nv_bfloat16* __restrict__ Alo,
    const __nv_bfloat16* __restrict__ Bhi, const __nv_bfloat16* __restrict__ Blo,
    const float* __restrict__ Aux, float* __restrict__ C,
    __nv_bfloat16* __restrict__ Chi, __nv_bfloat16* __restrict__ Clo) {
    extern __shared__ char sm[];
    const uint32_t smb = smem_u32(sm);
    const int tid = threadIdx.x;
    const int wid = tid >> 5;
    const int lane = tid & 31;
    const int bM = blockIdx.y * BM;
    const int bN = blockIdx.x * BN;

    // ---- cp.async tile loader: chunk c -> stage s
    const int lr = tid >> 1;                 // 0..127 row
    const int lq0 = (tid & 1) * 4;           // chunk base 0 or 4
    const uint32_t lxor = (uint32_t)(lr & 7);
    auto load_chunk = [&](int c, int s) {
        const uint32_t st = smb + s * STAGE_B;
        const size_t gA = (size_t)(bM + lr) * LD + c * BKE;
        const size_t gB = (size_t)(bN + lr) * LD + c * BKE;
        const uint32_t rowb = st + lr * 128;
#pragma unroll
        for (int i = 0; i < 4; i++) {
            const uint32_t q = lq0 + i;
            const uint32_t so = rowb + ((q ^ lxor) << 4);
            cpa16(so,              Ahi + gA + q * 8);
            cpa16(so + TILE_B,     Alo + gA + q * 8);
            cpa16(so + 2 * TILE_B, Bhi + gB + q * 8);
            cpa16(so + 3 * TILE_B, Blo + gB + q * 8);
        }
    };

    // ---- warp tiling: 4x2 warps, warp tile 32(M) x 64(N)
    const int wm = wid & 3;
    const int wn = wid >> 2;
    const int arow = wm * 32 + (lane & 15);
    const uint32_t aChunk = (uint32_t)(lane >> 4);       // 0/1 (k halves)
    const uint32_t aXor = (uint32_t)(arow & 7);
    const int brow0 = wn * 64 + (lane & 7) + ((lane >> 4) & 1) * 8;
    const uint32_t bChunk = (uint32_t)((lane >> 3) & 1);
    const uint32_t bXor = (uint32_t)(brow0 & 7);

    float acc[2][8][4];
#pragma unroll
    for (int i = 0; i < 2; i++)
#pragma unroll
        for (int j = 0; j < 8; j++)
#pragma unroll
            for (int q = 0; q < 4; q++) acc[i][j][q] = 0.f;

    load_chunk(0, 0);
    CP_COMMIT();
    load_chunk(1, 1);
    CP_COMMIT();

#pragma unroll 1
    for (int c = 0; c < NCH; c++) {
        CP_WAIT1();
        __syncthreads();
        if (c + 2 < NCH) load_chunk(c + 2, (c + 2) % STAGES);
        CP_COMMIT();

        const uint32_t st = smb + (c % STAGES) * STAGE_B;
#pragma unroll
        for (int kk = 0; kk < 4; kk++) {
            uint32_t ah[2][4], al[2][4];
#pragma unroll
            for (int mt = 0; mt < 2; mt++) {
                const uint32_t addr = st + (uint32_t)(arow + mt * 16) * 128 +
                                      (((kk * 2 + aChunk) ^ aXor) << 4);
                LDMX4(ah[mt], addr);
                LDMX4(al[mt], addr + TILE_B);
            }
            uint32_t bh[4][4], bl[4][4];
#pragma unroll
            for (int nt = 0; nt < 4; nt++) {
                const uint32_t addr = st + 2 * TILE_B +
                                      (uint32_t)(brow0 + nt * 16) * 128 +
                                      (((kk * 2 + bChunk) ^ bXor) << 4);
                LDMX4(bh[nt], addr);
                LDMX4(bl[nt], addr + TILE_B);
            }
#pragma unroll
            for (int mt = 0; mt < 2; mt++)
#pragma unroll
                for (int nt = 0; nt < 4; nt++) {
                    MMA16816(acc[mt][2 * nt],     ah[mt], bh[nt][0], bh[nt][1]);
                    MMA16816(acc[mt][2 * nt],     ah[mt], bl[nt][0], bl[nt][1]);
                    MMA16816(acc[mt][2 * nt],     al[mt], bh[nt][0], bh[nt][1]);
                    MMA16816(acc[mt][2 * nt + 1], ah[mt], bh[nt][2], bh[nt][3]);
                    MMA16816(acc[mt][2 * nt + 1], ah[mt], bl[nt][2], bl[nt][3]);
                    MMA16816(acc[mt][2 * nt + 1], al[mt], bh[nt][2], bh[nt][3]);
                }
        }
    }

    // ---- epilogue (register accumulators -> gmem)
    const int qrow = lane >> 2;
    const int qcol = (lane & 3) * 2;
#pragma unroll
    for (int mt = 0; mt < 2; mt++) {
#pragma unroll
        for (int h = 0; h < 2; h++) {
            const int row = bM + wm * 32 + mt * 16 + qrow + h * 8;
            const float* auxr = (MODE == 1 || MODE == 2) ? (Aux + (size_t)row * LD) : Aux;
            float* cr = WF32 ? (C + (size_t)row * LD) : nullptr;
#pragma unroll
            for (int n8 = 0; n8 < 8; n8++) {
                const int col = bN + wn * 64 + n8 * 8 + qcol;
                float v0 = acc[mt][n8][h * 2 + 0];
                float v1 = acc[mt][n8][h * 2 + 1];
                if (MODE == 1) {
                    float2 a2 = *(const float2*)(auxr + col);
                    v0 = NSC_C * v0 + NSC_B * a2.x;
                    v1 = NSC_C * v1 + NSC_B * a2.y;
                } else if (MODE == 2) {
                    float2 a2 = *(const float2*)(auxr + col);
                    v0 = fmaf(NSC_A, a2.x, v0);
                    v1 = fmaf(NSC_A, a2.y, v1);
                } else if (MODE == 3) {
                    float2 b2 = *(const float2*)(Aux + col);
                    v0 += b2.x;
                    v1 += b2.y;
                }
                if (WF32) {
                    float2 o; o.x = v0; o.y = v1;
                    *(float2*)(cr + col) = o;
                }
                if (WSPLIT) {
                    __nv_bfloat16 h0 = __float2bfloat16(v0);
                    __nv_bfloat16 h1 = __float2bfloat16(v1);
                    __nv_bfloat162 h2; h2.x = h0; h2.y = h1;
                    __nv_bfloat162 l2;
                    l2.x = __float2bfloat16(v0 - __bfloat162float(h0));
                    l2.y = __float2bfloat16(v1 - __bfloat162float(h1));
                    *(__nv_bfloat162*)(Chi + (size_t)row * LD + col) = h2;
                    *(__nv_bfloat162*)(Clo + (size_t)row * LD + col) = l2;
                }
            }
        }
    }
}

// ---------------- launch -----------------------------------------------------
extern "C" void kernel_launch(void* const* d_in, const int* in_sizes, int n_in,
                              void* d_out, int out_size) {
    const float* x = nullptr;
    const float* w = nullptr;
    const float* bias = nullptr;
    int x_size = 0;
    for (int i = 0; i < n_in; i++) {
        const int sz = in_sizes[i];
        if (sz == DIM) bias = (const float*)d_in[i];
        else if (sz == DIM * DIM) w = (const float*)d_in[i];
        else { x = (const float*)d_in[i]; x_size = sz; }
    }
    const int B_rows = x_size / DIM;  // 16384
    float* out = (float*)d_out;

    float *pX, *pX2, *pG;
    __nv_bfloat16 *pXhi, *pXlo, *pXThi, *pXTlo, *pGhi, *pGlo, *pBhi, *pBlo, *pxh, *pxl;
    cudaGetSymbolAddress((void**)&pX, g_X);
    cudaGetSymbolAddress((void**)&pX2, g_X2);
    cudaGetSymbolAddress((void**)&pG, g_G);
    cudaGetSymbolAddress((void**)&pXhi, g_Xhi);
    cudaGetSymbolAddress((void**)&pXlo, g_Xlo);
    cudaGetSymbolAddress((void**)&pXThi, g_XThi);
    cudaGetSymbolAddress((void**)&pXTlo, g_XTlo);
    cudaGetSymbolAddress((void**)&pGhi, g_Ghi);
    cudaGetSymbolAddress((void**)&pGlo, g_Glo);
    cudaGetSymbolAddress((void**)&pBhi, g_Bhi);
    cudaGetSymbolAddress((void**)&pBlo, g_Blo);
    cudaGetSymbolAddress((void**)&pxh, g_xbig_hi);
    cudaGetSymbolAddress((void**)&pxl, g_xbig_lo);

    cudaFuncSetAttribute(mmagemm<0, true, true>,  cudaFuncAttributeMaxDynamicSharedMemorySize, SMEM_TOTAL);
    cudaFuncSetAttribute(mmagemm<1, false, true>, cudaFuncAttributeMaxDynamicSharedMemorySize, SMEM_TOTAL);
    cudaFuncSetAttribute(mmagemm<2, true, true>,  cudaFuncAttributeMaxDynamicSharedMemorySize, SMEM_TOTAL);
    cudaFuncSetAttribute(mmagemm<3, true, false>, cudaFuncAttributeMaxDynamicSharedMemorySize, SMEM_TOTAL);

    const int n = DIM * DIM;
    norm_partial_kernel<<<256, 256>>>(w, n);
    norm_finalize_kernel<<<1, 256>>>();
    scale_split_kernel<<<1024, 256>>>(w, pX, pXhi, pXlo, n);
    strans_kernel<<<dim3(64, 64), dim3(32, 8)>>>(pX, pXThi, pXTlo);
    split_kernel<<<8192, 256>>>(x, pxh, pxl, B_rows * DIM);

    dim3 blk(256);
    dim3 gsq(DIM / BN, DIM / BM);  // (16, 16)
    for (int s = 0; s < 10; s++) {
        float* Xin = (s & 1) ? pX2 : pX;
        float* Xout = (s & 1) ? pX : pX2;
        // G = X @ X^T  -> G fp32 + split  (both operands K-major X)
        mmagemm<0, true, true><<<gsq, blk, SMEM_TOTAL>>>(
            pXhi, pXlo, pXhi, pXlo, nullptr, pG, pGhi, pGlo);
        // Bm = c*(G@G) + b*G  (G symmetric -> K-major both) -> split only
        mmagemm<1, false, true><<<gsq, blk, SMEM_TOTAL>>>(
            pGhi, pGlo, pGhi, pGlo, pG, nullptr, pBhi, pBlo);
        // X' = Bm@X + a*X  (Bm symmetric; B-operand = X^T, n-major) -> fp32 + split
        mmagemm<2, true, true><<<gsq, blk, SMEM_TOTAL>>>(
            pBhi, pBlo, pXThi, pXTlo, Xin, Xout, pXhi, pXlo);
        // X'^T split for next step's GEMM3 / final GEMM
        strans_kernel<<<dim3(64, 64), dim3(32, 8)>>>(Xout, pXThi, pXTlo);
    }
    // out = x @ Xfinal + bias  (B-operand = Xfinal^T split)
    dim3 gout(DIM / BN, B_rows / BM);  // (16, 128)
    mmagemm<3, true, false><<<gout, blk, SMEM_TOTAL>>>(
        pxh, pxl, pXThi, pXTlo, bias, out, nullptr, nullptr);
}

// round 5
// speedup vs baseline: 2.7024x; 1.3618x over previous
#include <cuda_runtime.h>
#include <cuda_bf16.h>
#include <cstdint>
#include <math.h>

static constexpr int DIM = 2048;
static constexpr int LD = 2048;
static constexpr float NSC_A = 3.4445f;
static constexpr float NSC_B = -4.7750f;
static constexpr float NSC_C = 2.0315f;

// ---------------- scratch (allocation-free: __device__ globals) -------------
__device__ __align__(256) float g_X[DIM * DIM];  // fp32 X0 (for initial transpose only)
__device__ __align__(256) __nv_bfloat16 g_Xhi [2][DIM * DIM];
__device__ __align__(256) __nv_bfloat16 g_Xlo [2][DIM * DIM];
__device__ __align__(256) __nv_bfloat16 g_XThi[2][DIM * DIM];
__device__ __align__(256) __nv_bfloat16 g_XTlo[2][DIM * DIM];
__device__ __align__(256) __nv_bfloat16 g_Ghi [DIM * DIM];
__device__ __align__(256) __nv_bfloat16 g_Glo [DIM * DIM];
__device__ __align__(256) __nv_bfloat16 g_Bhi [DIM * DIM];
__device__ __align__(256) __nv_bfloat16 g_Blo [DIM * DIM];
__device__ __align__(256) __nv_bfloat16 g_xbig_hi[16384 * DIM];
__device__ __align__(256) __nv_bfloat16 g_xbig_lo[16384 * DIM];
__device__ float g_partial[256];
__device__ float g_scale;

// ---------------- helpers ----------------------------------------------------
__device__ __forceinline__ uint32_t smem_u32(const void* p) {
    uint32_t a;
    asm("{ .reg .u64 t; cvta.to.shared.u64 t, %1; cvt.u32.u64 %0, t; }" : "=r"(a) : "l"(p));
    return a;
}
__device__ __forceinline__ void cpa16(uint32_t dst, const void* src) {
    asm volatile("cp.async.cg.shared.global [%0], [%1], 16;" :: "r"(dst), "l"(src) : "memory");
}
#define CP_COMMIT() asm volatile("cp.async.commit_group;" ::: "memory")
#define CP_WAIT1()  asm volatile("cp.async.wait_group 1;" ::: "memory")

#define LDMX4(r, a)                                                              \
    asm volatile("ldmatrix.sync.aligned.m8n8.x4.shared.b16 {%0,%1,%2,%3}, [%4];" \
        : "=r"((r)[0]), "=r"((r)[1]), "=r"((r)[2]), "=r"((r)[3]) : "r"(a))

#define MMA16816(acc, a, b0, b1)                                                  \
    asm volatile("mma.sync.aligned.m16n8k16.row.col.f32.bf16.bf16.f32 "           \
        "{%0,%1,%2,%3}, {%4,%5,%6,%7}, {%8,%9}, {%0,%1,%2,%3};"                   \
        : "+f"((acc)[0]), "+f"((acc)[1]), "+f"((acc)[2]), "+f"((acc)[3])          \
        : "r"((a)[0]), "r"((a)[1]), "r"((a)[2]), "r"((a)[3]), "r"(b0), "r"(b1))

__device__ __forceinline__ void store_split4(__nv_bfloat16* H, __nv_bfloat16* L, size_t off,
                                             float f0, float f1, float f2, float f3) {
    __nv_bfloat16 h0 = __float2bfloat16(f0), h1 = __float2bfloat16(f1);
    __nv_bfloat16 h2 = __float2bfloat16(f2), h3 = __float2bfloat16(f3);
    __nv_bfloat162 hA, hB, lA, lB;
    hA.x = h0; hA.y = h1; hB.x = h2; hB.y = h3;
    lA.x = __float2bfloat16(f0 - __bfloat162float(h0));
    lA.y = __float2bfloat16(f1 - __bfloat162float(h1));
    lB.x = __float2bfloat16(f2 - __bfloat162float(h2));
    lB.y = __float2bfloat16(f3 - __bfloat162float(h3));
    *(__nv_bfloat162*)(H + off) = hA;
    *(__nv_bfloat162*)(H + off + 2) = hB;
    *(__nv_bfloat162*)(L + off) = lA;
    *(__nv_bfloat162*)(L + off + 2) = lB;
}

// ---------------- small kernels ---------------------------------------------
__global__ void norm_partial_kernel(const float* __restrict__ w, int n) {
    __shared__ float sd[256];
    float s = 0.f;
    for (int i = blockIdx.x * blockDim.x + threadIdx.x; i < n; i += gridDim.x * blockDim.x) {
        float v = w[i];
        s = fmaf(v, v, s);
    }
    sd[threadIdx.x] = s;
    __syncthreads();
    for (int o = 128; o; o >>= 1) {
        if (threadIdx.x < o) sd[threadIdx.x] += sd[threadIdx.x + o];
        __syncthreads();
    }
    if (threadIdx.x == 0) g_partial[blockIdx.x] = sd[0];
}
__global__ void norm_finalize_kernel() {
    __shared__ float sd[256];
    sd[threadIdx.x] = g_partial[threadIdx.x];
    __syncthreads();
    for (int o = 128; o; o >>= 1) {
        if (threadIdx.x < o) sd[threadIdx.x] += sd[threadIdx.x + o];
        __syncthreads();
    }
    if (threadIdx.x == 0) g_scale = 1.0f / (sqrtf(sd[0]) + 1e-7f);
}
__global__ void scale_split_kernel(const float* __restrict__ w, float* __restrict__ X,
                                   __nv_bfloat16* __restrict__ hi, __nv_bfloat16* __restrict__ lo,
                                   int n) {
    const float s = g_scale;
    for (int i = blockIdx.x * blockDim.x + threadIdx.x; i < n; i += gridDim.x * blockDim.x) {
        float v = w[i] * s;
        X[i] = v;
        __nv_bfloat16 h = __float2bfloat16(v);
        hi[i] = h;
        lo[i] = __float2bfloat16(v - __bfloat162float(h));
    }
}
__global__ void split_kernel(const float* __restrict__ s, __nv_bfloat16* __restrict__ hi,
                             __nv_bfloat16* __restrict__ lo, int n) {
    for (int i = blockIdx.x * blockDim.x + threadIdx.x; i < n; i += gridDim.x * blockDim.x) {
        float v = s[i];
        __nv_bfloat16 h = __float2bfloat16(v);
        hi[i] = h;
        lo[i] = __float2bfloat16(v - __bfloat162float(h));
    }
}
// one-time transposed split of initial X
__global__ void strans_kernel(const float* __restrict__ src,
                              __nv_bfloat16* __restrict__ dhi, __nv_bfloat16* __restrict__ dlo) {
    __shared__ float t[32][33];
    int x = blockIdx.x * 32 + threadIdx.x;
    int y0 = blockIdx.y * 32;
    for (int j = threadIdx.y; j < 32; j += 8)
        t[j][threadIdx.x] = src[(size_t)(y0 + j) * LD + x];
    __syncthreads();
    int ox = blockIdx.y * 32 + threadIdx.x;
    for (int j = threadIdx.y; j < 32; j += 8) {
        float v = t[threadIdx.x][j];
        size_t o = (size_t)(blockIdx.x * 32 + j) * LD + ox;
        __nv_bfloat16 h = __float2bfloat16(v);
        dhi[o] = h;
        dlo[o] = __float2bfloat16(v - __bfloat162float(h));
    }
}

// ---------------- split-bf16 GEMM via mma.sync -------------------------------
// C[m,n] = sum_k A[m,k]*B[n,k]; K-major bf16 hi/lo pairs.
// acc = Ahi@Bhi + Ahi@Blo + Alo@Bhi  (fp32 accumulate)
// MODE 0: v = acc                 ; triangular grid; split out + mirror
// MODE 1: v = C*acc + B*aux(hi+lo); triangular grid; split out + mirror
// MODE 2: v = acc + A*aux(hi+lo)  ; full grid; split out + transposed split out
// MODE 3: v = acc + bias[n]       ; full grid; fp32 out (register epilogue)
static constexpr int BM = 128, BN = 128, BKE = 64;
static constexpr int NCH = DIM / BKE;            // 32 k-chunks
static constexpr int TILE_B = BM * 128;          // 16 KB
static constexpr int STAGE_B = 4 * TILE_B;       // 64 KB
static constexpr int STAGES = 3;
static constexpr int SMEM_TOTAL = STAGES * STAGE_B;  // 192 KB

template <int MODE>
__global__ __launch_bounds__(256, 1) void mmagemm(
    const __nv_bfloat16* __restrict__ Ahi, const __nv_bfloat16* __restrict__ Alo,
    const __nv_bfloat16* __restrict__ Bhi, const __nv_bfloat16* __restrict__ Blo,
    const __nv_bfloat16* __restrict__ auxhi, const __nv_bfloat16* __restrict__ auxlo,
    const float* __restrict__ bias,
    __nv_bfloat16* __restrict__ Chi, __nv_bfloat16* __restrict__ Clo,
    __nv_bfloat16* __restrict__ Thi, __nv_bfloat16* __restrict__ Tlo,
    float* __restrict__ Cf32) {
    extern __shared__ char sm[];
    const uint32_t smb = smem_u32(sm);
    const int tid = threadIdx.x;
    const int wid = tid >> 5;
    const int lane = tid & 31;

    int tm, tn;
    if (MODE == 0 || MODE == 1) {
        const int i = blockIdx.x;
        float fq = sqrtf(8.0f * (float)i + 1.0f);
        tn = (int)((fq - 1.0f) * 0.5f);
        while ((tn + 1) * (tn + 2) / 2 <= i) tn++;
        while (tn * (tn + 1) / 2 > i) tn--;
        tm = i - tn * (tn + 1) / 2;   // tm <= tn
    } else {
        tn = blockIdx.x;
        tm = blockIdx.y;
    }
    const int bM = tm * BM;
    const int bN = tn * BN;

    // ---- cp.async tile loader: chunk c -> stage s
    const int lr = tid >> 1;
    const int lq0 = (tid & 1) * 4;
    const uint32_t lxor = (uint32_t)(lr & 7);
    auto load_chunk = [&](int c, int s) {
        const uint32_t st = smb + s * STAGE_B;
        const size_t gA = (size_t)(bM + lr) * LD + c * BKE;
        const size_t gB = (size_t)(bN + lr) * LD + c * BKE;
        const uint32_t rowb = st + lr * 128;
#pragma unroll
        for (int i = 0; i < 4; i++) {
            const uint32_t q = lq0 + i;
            const uint32_t so = rowb + ((q ^ lxor) << 4);
            cpa16(so,              Ahi + gA + q * 8);
            cpa16(so + TILE_B,     Alo + gA + q * 8);
            cpa16(so + 2 * TILE_B, Bhi + gB + q * 8);
            cpa16(so + 3 * TILE_B, Blo + gB + q * 8);
        }
    };

    // ---- warp tiling: 4x2 warps, warp tile 32(M) x 64(N)
    const int wm = wid & 3;
    const int wn = wid >> 2;
    const int arow = wm * 32 + (lane & 15);
    const uint32_t aChunk = (uint32_t)(lane >> 4);
    const uint32_t aXor = (uint32_t)(arow & 7);
    const int brow0 = wn * 64 + (lane & 7) + ((lane >> 4) & 1) * 8;
    const uint32_t bChunk = (uint32_t)((lane >> 3) & 1);
    const uint32_t bXor = (uint32_t)(brow0 & 7);

    float acc[2][8][4];
#pragma unroll
    for (int i = 0; i < 2; i++)
#pragma unroll
        for (int j = 0; j < 8; j++)
#pragma unroll
            for (int q = 0; q < 4; q++) acc[i][j][q] = 0.f;

    load_chunk(0, 0);
    CP_COMMIT();
    load_chunk(1, 1);
    CP_COMMIT();

#pragma unroll 1
    for (int c = 0; c < NCH; c++) {
        CP_WAIT1();
        __syncthreads();
        if (c + 2 < NCH) load_chunk(c + 2, (c + 2) % STAGES);
        CP_COMMIT();

        const uint32_t st = smb + (c % STAGES) * STAGE_B;
#pragma unroll
        for (int kk = 0; kk < 4; kk++) {
            uint32_t ah[2][4], al[2][4];
#pragma unroll
            for (int mt = 0; mt < 2; mt++) {
                const uint32_t addr = st + (uint32_t)(arow + mt * 16) * 128 +
                                      (((kk * 2 + aChunk) ^ aXor) << 4);
                LDMX4(ah[mt], addr);
                LDMX4(al[mt], addr + TILE_B);
            }
            uint32_t bh[4][4], bl[4][4];
#pragma unroll
            for (int nt = 0; nt < 4; nt++) {
                const uint32_t addr = st + 2 * TILE_B +
                                      (uint32_t)(brow0 + nt * 16) * 128 +
                                      (((kk * 2 + bChunk) ^ bXor) << 4);
                LDMX4(bh[nt], addr);
                LDMX4(bl[nt], addr + TILE_B);
            }
#pragma unroll
            for (int mt = 0; mt < 2; mt++)
#pragma unroll
                for (int nt = 0; nt < 4; nt++) {
                    MMA16816(acc[mt][2 * nt],     ah[mt], bh[nt][0], bh[nt][1]);
                    MMA16816(acc[mt][2 * nt],     ah[mt], bl[nt][0], bl[nt][1]);
                    MMA16816(acc[mt][2 * nt],     al[mt], bh[nt][0], bh[nt][1]);
                    MMA16816(acc[mt][2 * nt + 1], ah[mt], bh[nt][2], bh[nt][3]);
                    MMA16816(acc[mt][2 * nt + 1], ah[mt], bl[nt][2], bl[nt][3]);
                    MMA16816(acc[mt][2 * nt + 1], al[mt], bh[nt][2], bh[nt][3]);
                }
        }
    }

    const int qrow = lane >> 2;
    const int qcol = (lane & 3) * 2;

    if (MODE == 3) {
        // register epilogue, fp32 out + bias
#pragma unroll
        for (int mt = 0; mt < 2; mt++) {
#pragma unroll
            for (int h = 0; h < 2; h++) {
                const int row = bM + wm * 32 + mt * 16 + qrow + h * 8;
                float* cr = Cf32 + (size_t)row * LD;
#pragma unroll
                for (int n8 = 0; n8 < 8; n8++) {
                    const int col = bN + wn * 64 + n8 * 8 + qcol;
                    float2 b2 = *(const float2*)(bias + col);
                    float2 o;
                    o.x = acc[mt][n8][h * 2 + 0] + b2.x;
                    o.y = acc[mt][n8][h * 2 + 1] + b2.y;
                    *(float2*)(cr + col) = o;
                }
            }
        }
        return;
    }

    // ---- staged epilogue: fragments (+aux) -> swizzled smem stage ----------
    float* stage = (float*)sm;
    __syncthreads();  // all warps done reading operand tiles
#pragma unroll
    for (int mt = 0; mt < 2; mt++) {
#pragma unroll
        for (int h = 0; h < 2; h++) {
            const int rl = wm * 32 + mt * 16 + qrow + h * 8;
#pragma unroll
            for (int n8 = 0; n8 < 8; n8++) {
                const int cl = wn * 64 + n8 * 8 + qcol;
                float v0 = acc[mt][n8][h * 2 + 0];
                float v1 = acc[mt][n8][h * 2 + 1];
                if (MODE == 1 || MODE == 2) {
                    const size_t ao = (size_t)(bM + rl) * LD + bN + cl;
                    __nv_bfloat162 a2 = *(const __nv_bfloat162*)(auxhi + ao);
                    __nv_bfloat162 l2 = *(const __nv_bfloat162*)(auxlo + ao);
                    const float x0 = __bfloat162float(a2.x) + __bfloat162float(l2.x);
                    const float x1 = __bfloat162float(a2.y) + __bfloat162float(l2.y);
                    if (MODE == 1) {
                        v0 = NSC_C * v0 + NSC_B * x0;
                        v1 = NSC_C * v1 + NSC_B * x1;
                    } else {
                        v0 = fmaf(NSC_A, x0, v0);
                        v1 = fmaf(NSC_A, x1, v1);
                    }
                }
                stage[rl * 128 + (cl ^ (rl & 31))] = v0;
                stage[rl * 128 + ((cl + 1) ^ (rl & 31))] = v1;
            }
        }
    }
    __syncthreads();

    // ---- writes: warp w handles rows w*16..w*16+15, lane covers 4 cols -----
    const int c4 = lane * 4;
    // normal orientation
#pragma unroll 4
    for (int rr = 0; rr < 16; rr++) {
        const int r = wid * 16 + rr;
        const int rx = r & 31;
        float f0 = stage[r * 128 + ((c4 + 0) ^ rx)];
        float f1 = stage[r * 128 + ((c4 + 1) ^ rx)];
        float f2 = stage[r * 128 + ((c4 + 2) ^ rx)];
        float f3 = stage[r * 128 + ((c4 + 3) ^ rx)];
        store_split4(Chi, Clo, (size_t)(bM + r) * LD + bN + c4, f0, f1, f2, f3);
    }
    // mirrored / transposed orientation
    if (MODE == 2 || tm != tn) {
        __nv_bfloat16* Dh = (MODE == 2) ? Thi : Chi;
        __nv_bfloat16* Dl = (MODE == 2) ? Tlo : Clo;
#pragma unroll 4
        for (int rr = 0; rr < 16; rr++) {
            const int r = wid * 16 + rr;  // output row within mirror block
            float f0 = stage[(c4 + 0) * 128 + (r ^ ((c4 + 0) & 31))];
            float f1 = stage[(c4 + 1) * 128 + (r ^ ((c4 + 1) & 31))];
            float f2 = stage[(c4 + 2) * 128 + (r ^ ((c4 + 2) & 31))];
            float f3 = stage[(c4 + 3) * 128 + (r ^ ((c4 + 3) & 31))];
            store_split4(Dh, Dl, (size_t)(bN + r) * LD + bM + c4, f0, f1, f2, f3);
        }
    }
}

// ---------------- launch -----------------------------------------------------
extern "C" void kernel_launch(void* const* d_in, const int* in_sizes, int n_in,
                              void* d_out, int out_size) {
    const float* x = nullptr;
    const float* w = nullptr;
    const float* bias = nullptr;
    int x_size = 0;
    for (int i = 0; i < n_in; i++) {
        const int sz = in_sizes[i];
        if (sz == DIM) bias = (const float*)d_in[i];
        else if (sz == DIM * DIM) w = (const float*)d_in[i];
        else { x = (const float*)d_in[i]; x_size = sz; }
    }
    const int B_rows = x_size / DIM;  // 16384
    float* out = (float*)d_out;

    float* pX;
    __nv_bfloat16 *pXhi[2], *pXlo[2], *pXThi[2], *pXTlo[2];
    __nv_bfloat16 *pGhi, *pGlo, *pBhi, *pBlo, *pxh, *pxl;
    cudaGetSymbolAddress((void**)&pX, g_X);
    {
        __nv_bfloat16* base;
        cudaGetSymbolAddress((void**)&base, g_Xhi);
        pXhi[0] = base; pXhi[1] = base + DIM * DIM;
        cudaGetSymbolAddress((void**)&base, g_Xlo);
        pXlo[0] = base; pXlo[1] = base + DIM * DIM;
        cudaGetSymbolAddress((void**)&base, g_XThi);
        pXThi[0] = base; pXThi[1] = base + DIM * DIM;
        cudaGetSymbolAddress((void**)&base, g_XTlo);
        pXTlo[0] = base; pXTlo[1] = base + DIM * DIM;
    }
    cudaGetSymbolAddress((void**)&pGhi, g_Ghi);
    cudaGetSymbolAddress((void**)&pGlo, g_Glo);
    cudaGetSymbolAddress((void**)&pBhi, g_Bhi);
    cudaGetSymbolAddress((void**)&pBlo, g_Blo);
    cudaGetSymbolAddress((void**)&pxh, g_xbig_hi);
    cudaGetSymbolAddress((void**)&pxl, g_xbig_lo);

    cudaFuncSetAttribute(mmagemm<0>, cudaFuncAttributeMaxDynamicSharedMemorySize, SMEM_TOTAL);
    cudaFuncSetAttribute(mmagemm<1>, cudaFuncAttributeMaxDynamicSharedMemorySize, SMEM_TOTAL);
    cudaFuncSetAttribute(mmagemm<2>, cudaFuncAttributeMaxDynamicSharedMemorySize, SMEM_TOTAL);
    cudaFuncSetAttribute(mmagemm<3>, cudaFuncAttributeMaxDynamicSharedMemorySize, SMEM_TOTAL);

    const int n = DIM * DIM;
    norm_partial_kernel<<<256, 256>>>(w, n);
    norm_finalize_kernel<<<1, 256>>>();
    scale_split_kernel<<<1024, 256>>>(w, pX, pXhi[0], pXlo[0], n);
    strans_kernel<<<dim3(64, 64), dim3(32, 8)>>>(pX, pXThi[0], pXTlo[0]);
    split_kernel<<<8192, 256>>>(x, pxh, pxl, B_rows * DIM);

    dim3 blk(256);
    const int NT = DIM / BM;                 // 16
    dim3 gtri(NT * (NT + 1) / 2, 1);         // 136 CTAs (single wave)
    dim3 gsq(NT, NT);                        // 256 CTAs
    for (int s = 0; s < 10; s++) {
        const int c0 = s & 1, n1 = c0 ^ 1;
        // G = X @ X^T (symmetric, triangular + mirror)
        mmagemm<0><<<gtri, blk, SMEM_TOTAL>>>(
            pXhi[c0], pXlo[c0], pXhi[c0], pXlo[c0],
            nullptr, nullptr, nullptr, pGhi, pGlo, nullptr, nullptr, nullptr);
        // Bm = c*(G@G) + b*G (symmetric, triangular + mirror)
        mmagemm<1><<<gtri, blk, SMEM_TOTAL>>>(
            pGhi, pGlo, pGhi, pGlo,
            pGhi, pGlo, nullptr, pBhi, pBlo, nullptr, nullptr, nullptr);
        // X' = Bm@X + a*X ; writes X'[n1] split + X'^T[n1] split
        mmagemm<2><<<gsq, blk, SMEM_TOTAL>>>(
            pBhi, pBlo, pXThi[c0], pXTlo[c0],
            pXhi[c0], pXlo[c0], nullptr,
            pXhi[n1], pXlo[n1], pXThi[n1], pXTlo[n1], nullptr);
    }
    // out = x @ Xfinal + bias  (Xfinal^T split is in slot 0 after 10 iters)
    dim3 gout(NT, B_rows / BM);  // (16, 128)
    mmagemm<3><<<gout, blk, SMEM_TOTAL>>>(
        pxh, pxl, pXThi[0], pXTlo[0],
        nullptr, nullptr, bias, nullptr, nullptr, nullptr, nullptr, out);
}

// round 6
// speedup vs baseline: 2.9268x; 1.0830x over previous
#include <cuda_runtime.h>
#include <cuda_bf16.h>
#include <cstdint>
#include <math.h>

static constexpr int DIM = 2048;
static constexpr int LD = 2048;
static constexpr float NSC_A = 3.4445f;
static constexpr float NSC_B = -4.7750f;
static constexpr float NSC_C = 2.0315f;

// ---------------- scratch (allocation-free: __device__ globals) -------------
__device__ __align__(256) float g_X[DIM * DIM];
__device__ __align__(256) __nv_bfloat16 g_Xhi [2][DIM * DIM];
__device__ __align__(256) __nv_bfloat16 g_Xlo [2][DIM * DIM];
__device__ __align__(256) __nv_bfloat16 g_XThi[2][DIM * DIM];
__device__ __align__(256) __nv_bfloat16 g_XTlo[2][DIM * DIM];
__device__ __align__(256) __nv_bfloat16 g_Ghi [DIM * DIM];
__device__ __align__(256) __nv_bfloat16 g_Glo [DIM * DIM];
__device__ __align__(256) __nv_bfloat16 g_Bhi [DIM * DIM];
__device__ __align__(256) __nv_bfloat16 g_Blo [DIM * DIM];
__device__ __align__(256) __nv_bfloat16 g_xbig_hi[16384 * DIM];
__device__ __align__(256) __nv_bfloat16 g_xbig_lo[16384 * DIM];
__device__ float g_partial[256];
__device__ float g_scale;

// ---------------- helpers ----------------------------------------------------
__device__ __forceinline__ uint32_t smem_u32(const void* p) {
    uint32_t a;
    asm("{ .reg .u64 t; cvta.to.shared.u64 t, %1; cvt.u32.u64 %0, t; }" : "=r"(a) : "l"(p));
    return a;
}
__device__ __forceinline__ void cpa16(uint32_t dst, const void* src) {
    asm volatile("cp.async.cg.shared.global [%0], [%1], 16;" :: "r"(dst), "l"(src) : "memory");
}
#define CP_COMMIT() asm volatile("cp.async.commit_group;" ::: "memory")
#define CP_WAIT1()  asm volatile("cp.async.wait_group 1;" ::: "memory")
#define CP_WAIT0()  asm volatile("cp.async.wait_group 0;" ::: "memory")

#define LDMX4(r, a)                                                              \
    asm volatile("ldmatrix.sync.aligned.m8n8.x4.shared.b16 {%0,%1,%2,%3}, [%4];" \
        : "=r"((r)[0]), "=r"((r)[1]), "=r"((r)[2]), "=r"((r)[3]) : "r"(a))

#define MMA16816(acc, a, b0, b1)                                                  \
    asm volatile("mma.sync.aligned.m16n8k16.row.col.f32.bf16.bf16.f32 "           \
        "{%0,%1,%2,%3}, {%4,%5,%6,%7}, {%8,%9}, {%0,%1,%2,%3};"                   \
        : "+f"((acc)[0]), "+f"((acc)[1]), "+f"((acc)[2]), "+f"((acc)[3])          \
        : "r"((a)[0]), "r"((a)[1]), "r"((a)[2]), "r"((a)[3]), "r"(b0), "r"(b1))

__device__ __forceinline__ void store_split4(__nv_bfloat16* H, __nv_bfloat16* L, size_t off,
                                             float f0, float f1, float f2, float f3) {
    __nv_bfloat16 h0 = __float2bfloat16(f0), h1 = __float2bfloat16(f1);
    __nv_bfloat16 h2 = __float2bfloat16(f2), h3 = __float2bfloat16(f3);
    __nv_bfloat162 hA, hB, lA, lB;
    hA.x = h0; hA.y = h1; hB.x = h2; hB.y = h3;
    lA.x = __float2bfloat16(f0 - __bfloat162float(h0));
    lA.y = __float2bfloat16(f1 - __bfloat162float(h1));
    lB.x = __float2bfloat16(f2 - __bfloat162float(h2));
    lB.y = __float2bfloat16(f3 - __bfloat162float(h3));
    *(__nv_bfloat162*)(H + off) = hA;
    *(__nv_bfloat162*)(H + off + 2) = hB;
    *(__nv_bfloat162*)(L + off) = lA;
    *(__nv_bfloat162*)(L + off + 2) = lB;
}
__device__ __forceinline__ void store_split2(__nv_bfloat16* H, __nv_bfloat16* L, size_t off,
                                             float f0, float f1) {
    __nv_bfloat16 h0 = __float2bfloat16(f0), h1 = __float2bfloat16(f1);
    __nv_bfloat162 h2, l2;
    h2.x = h0; h2.y = h1;
    l2.x = __float2bfloat16(f0 - __bfloat162float(h0));
    l2.y = __float2bfloat16(f1 - __bfloat162float(h1));
    *(__nv_bfloat162*)(H + off) = h2;
    *(__nv_bfloat162*)(L + off) = l2;
}

// ---------------- small kernels ---------------------------------------------
__global__ void norm_partial_kernel(const float* __restrict__ w, int n) {
    __shared__ float sd[256];
    float s = 0.f;
    for (int i = blockIdx.x * blockDim.x + threadIdx.x; i < n; i += gridDim.x * blockDim.x) {
        float v = w[i];
        s = fmaf(v, v, s);
    }
    sd[threadIdx.x] = s;
    __syncthreads();
    for (int o = 128; o; o >>= 1) {
        if (threadIdx.x < o) sd[threadIdx.x] += sd[threadIdx.x + o];
        __syncthreads();
    }
    if (threadIdx.x == 0) g_partial[blockIdx.x] = sd[0];
}
__global__ void norm_finalize_kernel() {
    __shared__ float sd[256];
    sd[threadIdx.x] = g_partial[threadIdx.x];
    __syncthreads();
    for (int o = 128; o; o >>= 1) {
        if (threadIdx.x < o) sd[threadIdx.x] += sd[threadIdx.x + o];
        __syncthreads();
    }
    if (threadIdx.x == 0) g_scale = 1.0f / (sqrtf(sd[0]) + 1e-7f);
}
__global__ void scale_split_kernel(const float* __restrict__ w, float* __restrict__ X,
                                   __nv_bfloat16* __restrict__ hi, __nv_bfloat16* __restrict__ lo,
                                   int n) {
    const float s = g_scale;
    for (int i = blockIdx.x * blockDim.x + threadIdx.x; i < n; i += gridDim.x * blockDim.x) {
        float v = w[i] * s;
        X[i] = v;
        __nv_bfloat16 h = __float2bfloat16(v);
        hi[i] = h;
        lo[i] = __float2bfloat16(v - __bfloat162float(h));
    }
}
__global__ void split_kernel(const float* __restrict__ s, __nv_bfloat16* __restrict__ hi,
                             __nv_bfloat16* __restrict__ lo, int n) {
    for (int i = blockIdx.x * blockDim.x + threadIdx.x; i < n; i += gridDim.x * blockDim.x) {
        float v = s[i];
        __nv_bfloat16 h = __float2bfloat16(v);
        hi[i] = h;
        lo[i] = __float2bfloat16(v - __bfloat162float(h));
    }
}
__global__ void strans_kernel(const float* __restrict__ src,
                              __nv_bfloat16* __restrict__ dhi, __nv_bfloat16* __restrict__ dlo) {
    __shared__ float t[32][33];
    int x = blockIdx.x * 32 + threadIdx.x;
    int y0 = blockIdx.y * 32;
    for (int j = threadIdx.y; j < 32; j += 8)
        t[j][threadIdx.x] = src[(size_t)(y0 + j) * LD + x];
    __syncthreads();
    int ox = blockIdx.y * 32 + threadIdx.x;
    for (int j = threadIdx.y; j < 32; j += 8) {
        float v = t[threadIdx.x][j];
        size_t o = (size_t)(blockIdx.x * 32 + j) * LD + ox;
        __nv_bfloat16 h = __float2bfloat16(v);
        dhi[o] = h;
        dlo[o] = __float2bfloat16(v - __bfloat162float(h));
    }
}

// ============ TRIANGULAR kernel (modes 0/1) — unchanged from R5 ==============
static constexpr int BM = 128, BN = 128, BKE = 64;
static constexpr int NCH = DIM / BKE;
static constexpr int TILE_B = BM * 128;
static constexpr int STAGE_B = 4 * TILE_B;
static constexpr int STAGES = 3;
static constexpr int SMEM_TOTAL = STAGES * STAGE_B;  // 192 KB

template <int MODE>
__global__ __launch_bounds__(256, 1) void mmagemm(
    const __nv_bfloat16* __restrict__ Ahi, const __nv_bfloat16* __restrict__ Alo,
    const __nv_bfloat16* __restrict__ Bhi, const __nv_bfloat16* __restrict__ Blo,
    const __nv_bfloat16* __restrict__ auxhi, const __nv_bfloat16* __restrict__ auxlo,
    __nv_bfloat16* __restrict__ Chi, __nv_bfloat16* __restrict__ Clo) {
    extern __shared__ char sm[];
    const uint32_t smb = smem_u32(sm);
    const int tid = threadIdx.x;
    const int wid = tid >> 5;
    const int lane = tid & 31;

    const int i = blockIdx.x;
    float fq = sqrtf(8.0f * (float)i + 1.0f);
    int tn = (int)((fq - 1.0f) * 0.5f);
    while ((tn + 1) * (tn + 2) / 2 <= i) tn++;
    while (tn * (tn + 1) / 2 > i) tn--;
    int tm = i - tn * (tn + 1) / 2;
    const int bM = tm * BM;
    const int bN = tn * BN;

    const int lr = tid >> 1;
    const int lq0 = (tid & 1) * 4;
    const uint32_t lxor = (uint32_t)(lr & 7);
    auto load_chunk = [&](int c, int s) {
        const uint32_t st = smb + s * STAGE_B;
        const size_t gA = (size_t)(bM + lr) * LD + c * BKE;
        const size_t gB = (size_t)(bN + lr) * LD + c * BKE;
        const uint32_t rowb = st + lr * 128;
#pragma unroll
        for (int q0 = 0; q0 < 4; q0++) {
            const uint32_t q = lq0 + q0;
            const uint32_t so = rowb + ((q ^ lxor) << 4);
            cpa16(so,              Ahi + gA + q * 8);
            cpa16(so + TILE_B,     Alo + gA + q * 8);
            cpa16(so + 2 * TILE_B, Bhi + gB + q * 8);
            cpa16(so + 3 * TILE_B, Blo + gB + q * 8);
        }
    };

    const int wm = wid & 3;
    const int wn = wid >> 2;
    const int arow = wm * 32 + (lane & 15);
    const uint32_t aChunk = (uint32_t)(lane >> 4);
    const uint32_t aXor = (uint32_t)(arow & 7);
    const int brow0 = wn * 64 + (lane & 7) + ((lane >> 4) & 1) * 8;
    const uint32_t bChunk = (uint32_t)((lane >> 3) & 1);
    const uint32_t bXor = (uint32_t)(brow0 & 7);

    float acc[2][8][4];
#pragma unroll
    for (int a = 0; a < 2; a++)
#pragma unroll
        for (int b = 0; b < 8; b++)
#pragma unroll
            for (int q = 0; q < 4; q++) acc[a][b][q] = 0.f;

    load_chunk(0, 0);
    CP_COMMIT();
    load_chunk(1, 1);
    CP_COMMIT();

#pragma unroll 1
    for (int c = 0; c < NCH; c++) {
        CP_WAIT1();
        __syncthreads();
        if (c + 2 < NCH) load_chunk(c + 2, (c + 2) % STAGES);
        CP_COMMIT();

        const uint32_t st = smb + (c % STAGES) * STAGE_B;
#pragma unroll
        for (int kk = 0; kk < 4; kk++) {
            uint32_t ah[2][4], al[2][4];
#pragma unroll
            for (int mt = 0; mt < 2; mt++) {
                const uint32_t addr = st + (uint32_t)(arow + mt * 16) * 128 +
                                      (((kk * 2 + aChunk) ^ aXor) << 4);
                LDMX4(ah[mt], addr);
                LDMX4(al[mt], addr + TILE_B);
            }
            uint32_t bh[4][4], bl[4][4];
#pragma unroll
            for (int nt = 0; nt < 4; nt++) {
                const uint32_t addr = st + 2 * TILE_B +
                                      (uint32_t)(brow0 + nt * 16) * 128 +
                                      (((kk * 2 + bChunk) ^ bXor) << 4);
                LDMX4(bh[nt], addr);
                LDMX4(bl[nt], addr + TILE_B);
            }
#pragma unroll
            for (int mt = 0; mt < 2; mt++)
#pragma unroll
                for (int nt = 0; nt < 4; nt++) {
                    MMA16816(acc[mt][2 * nt],     ah[mt], bh[nt][0], bh[nt][1]);
                    MMA16816(acc[mt][2 * nt],     ah[mt], bl[nt][0], bl[nt][1]);
                    MMA16816(acc[mt][2 * nt],     al[mt], bh[nt][0], bh[nt][1]);
                    MMA16816(acc[mt][2 * nt + 1], ah[mt], bh[nt][2], bh[nt][3]);
                    MMA16816(acc[mt][2 * nt + 1], ah[mt], bl[nt][2], bl[nt][3]);
                    MMA16816(acc[mt][2 * nt + 1], al[mt], bh[nt][2], bh[nt][3]);
                }
        }
    }

    const int qrow = lane >> 2;
    const int qcol = (lane & 3) * 2;
    float* stage = (float*)sm;
    __syncthreads();
#pragma unroll
    for (int mt = 0; mt < 2; mt++) {
#pragma unroll
        for (int h = 0; h < 2; h++) {
            const int rl = wm * 32 + mt * 16 + qrow + h * 8;
#pragma unroll
            for (int n8 = 0; n8 < 8; n8++) {
                const int cl = wn * 64 + n8 * 8 + qcol;
                float v0 = acc[mt][n8][h * 2 + 0];
                float v1 = acc[mt][n8][h * 2 + 1];
                if (MODE == 1) {
                    const size_t ao = (size_t)(bM + rl) * LD + bN + cl;
                    __nv_bfloat162 a2 = *(const __nv_bfloat162*)(auxhi + ao);
                    __nv_bfloat162 l2 = *(const __nv_bfloat162*)(auxlo + ao);
                    const float x0 = __bfloat162float(a2.x) + __bfloat162float(l2.x);
                    const float x1 = __bfloat162float(a2.y) + __bfloat162float(l2.y);
                    v0 = NSC_C * v0 + NSC_B * x0;
                    v1 = NSC_C * v1 + NSC_B * x1;
                }
                stage[rl * 128 + (cl ^ (rl & 31))] = v0;
                stage[rl * 128 + ((cl + 1) ^ (rl & 31))] = v1;
            }
        }
    }
    __syncthreads();

    const int c4 = lane * 4;
#pragma unroll 4
    for (int rr = 0; rr < 16; rr++) {
        const int r = wid * 16 + rr;
        const int rx = r & 31;
        float f0 = stage[r * 128 + ((c4 + 0) ^ rx)];
        float f1 = stage[r * 128 + ((c4 + 1) ^ rx)];
        float f2 = stage[r * 128 + ((c4 + 2) ^ rx)];
        float f3 = stage[r * 128 + ((c4 + 3) ^ rx)];
        store_split4(Chi, Clo, (size_t)(bM + r) * LD + bN + c4, f0, f1, f2, f3);
    }
    if (tm != tn) {
#pragma unroll 4
        for (int rr = 0; rr < 16; rr++) {
            const int r = wid * 16 + rr;
            float f0 = stage[(c4 + 0) * 128 + (r ^ ((c4 + 0) & 31))];
            float f1 = stage[(c4 + 1) * 128 + (r ^ ((c4 + 1) & 31))];
            float f2 = stage[(c4 + 2) * 128 + (r ^ ((c4 + 2) & 31))];
            float f3 = stage[(c4 + 3) * 128 + (r ^ ((c4 + 3) & 31))];
            store_split4(Chi, Clo, (size_t)(bN + r) * LD + bM + c4, f0, f1, f2, f3);
        }
    }
}

// ============ BIG kernel (modes 2/3): CTA 128x256, warp tile 64x64 ===========
// MODE 2: v = acc + NSC_A*aux(hi+lo); writes split C + transposed split T
// MODE 3: v = acc + bias[n]         ; writes fp32 C
static constexpr int B2M = 128, B2N = 256, B2K = 32;
static constexpr int NC2 = DIM / B2K;                    // 64 chunks
static constexpr int PITCH = 80;                         // 64B data + 16B pad
static constexpr int A2_B = B2M * PITCH;                 // 10240
static constexpr int B2_B = B2N * PITCH;                 // 20480
static constexpr int STG2 = 2 * A2_B + 2 * B2_B;         // 61440
static constexpr int NSTG2 = 3;
static constexpr int SMEM_BIG = NSTG2 * STG2;            // 184320

template <int MODE>
__global__ __launch_bounds__(256, 1) void mmagemm_big(
    const __nv_bfloat16* __restrict__ Ahi, const __nv_bfloat16* __restrict__ Alo,
    const __nv_bfloat16* __restrict__ Bhi, const __nv_bfloat16* __restrict__ Blo,
    const __nv_bfloat16* __restrict__ auxhi, const __nv_bfloat16* __restrict__ auxlo,
    const float* __restrict__ bias,
    __nv_bfloat16* __restrict__ Chi, __nv_bfloat16* __restrict__ Clo,
    __nv_bfloat16* __restrict__ Thi, __nv_bfloat16* __restrict__ Tlo,
    float* __restrict__ Cf32) {
    extern __shared__ char sm[];
    const uint32_t smb = smem_u32(sm);
    const int tid = threadIdx.x;
    const int wid = tid >> 5;
    const int lane = tid & 31;
    const int bM = blockIdx.y * B2M;
    const int bN = blockIdx.x * B2N;

    // loader: 384 rows x 4 chunks of 16B, hi+lo => 6 iterations of (2 cpa16)
    auto load_chunk = [&](int c, int s) {
        const uint32_t st = smb + s * STG2;
#pragma unroll
        for (int it = 0; it < 6; it++) {
            const int i = tid + it * 256;   // 0..1535
            const int row = i >> 2;
            const int q = i & 3;
            if (row < B2M) {
                const size_t g = (size_t)(bM + row) * LD + c * B2K + q * 8;
                const uint32_t so = st + row * PITCH + q * 16;
                cpa16(so, Ahi + g);
                cpa16(so + A2_B, Alo + g);
            } else {
                const int br = row - B2M;
                const size_t g = (size_t)(bN + br) * LD + c * B2K + q * 8;
                const uint32_t so = st + 2 * A2_B + br * PITCH + q * 16;
                cpa16(so, Bhi + g);
                cpa16(so + B2_B, Blo + g);
            }
        }
    };

    // warp grid 2(m) x 4(n); warp tile 64x64
    const int wm = wid & 1;
    const int wn = wid >> 1;
    const int arowL = wm * 64 + (lane & 15);           // + mt*16
    const int aChunk = lane >> 4;                      // k16-half
    const int browL = wn * 64 + (lane & 7) + ((lane >> 4) & 1) * 8;  // + nt*16
    const int bChunk = (lane >> 3) & 1;

    float acc[4][8][4];
#pragma unroll
    for (int a = 0; a < 4; a++)
#pragma unroll
        for (int b = 0; b < 8; b++)
#pragma unroll
            for (int q = 0; q < 4; q++) acc[a][b][q] = 0.f;

    load_chunk(0, 0);
    CP_COMMIT();
    load_chunk(1, 1);
    CP_COMMIT();

#pragma unroll 1
    for (int c = 0; c < NC2; c++) {
        if (c + 1 < NC2) CP_WAIT1(); else CP_WAIT0();
        __syncthreads();
        if (c + 2 < NC2) { load_chunk(c + 2, (c + 2) % NSTG2); CP_COMMIT(); }

        const uint32_t st = smb + (c % NSTG2) * STG2;
#pragma unroll
        for (int kk = 0; kk < 2; kk++) {
            uint32_t ah[4][4], al[4][4];
#pragma unroll
            for (int mt = 0; mt < 4; mt++) {
                const uint32_t addr = st + (uint32_t)(arowL + mt * 16) * PITCH +
                                      (uint32_t)(kk * 2 + aChunk) * 16;
                LDMX4(ah[mt], addr);
                LDMX4(al[mt], addr + A2_B);
            }
            uint32_t bh[4][4], bl[4][4];
#pragma unroll
            for (int nt = 0; nt < 4; nt++) {
                const uint32_t addr = st + 2 * A2_B +
                                      (uint32_t)(browL + nt * 16) * PITCH +
                                      (uint32_t)(kk * 2 + bChunk) * 16;
                LDMX4(bh[nt], addr);
                LDMX4(bl[nt], addr + B2_B);
            }
#pragma unroll
            for (int mt = 0; mt < 4; mt++)
#pragma unroll
                for (int nt = 0; nt < 4; nt++) {
                    MMA16816(acc[mt][2 * nt],     ah[mt], bh[nt][0], bh[nt][1]);
                    MMA16816(acc[mt][2 * nt],     ah[mt], bl[nt][0], bl[nt][1]);
                    MMA16816(acc[mt][2 * nt],     al[mt], bh[nt][0], bh[nt][1]);
                    MMA16816(acc[mt][2 * nt + 1], ah[mt], bh[nt][2], bh[nt][3]);
                    MMA16816(acc[mt][2 * nt + 1], ah[mt], bl[nt][2], bl[nt][3]);
                    MMA16816(acc[mt][2 * nt + 1], al[mt], bh[nt][2], bh[nt][3]);
                }
        }
    }

    const int qrow = lane >> 2;
    const int qcol = (lane & 3) * 2;

    if (MODE == 3) {
#pragma unroll
        for (int mt = 0; mt < 4; mt++) {
#pragma unroll
            for (int h = 0; h < 2; h++) {
                const int row = bM + wm * 64 + mt * 16 + qrow + h * 8;
                float* cr = Cf32 + (size_t)row * LD;
#pragma unroll
                for (int n8 = 0; n8 < 8; n8++) {
                    const int col = bN + wn * 64 + n8 * 8 + qcol;
                    float2 b2 = *(const float2*)(bias + col);
                    float2 o;
                    o.x = acc[mt][n8][h * 2 + 0] + b2.x;
                    o.y = acc[mt][n8][h * 2 + 1] + b2.y;
                    *(float2*)(cr + col) = o;
                }
            }
        }
        return;
    }

    // MODE 2: stage 128x256 fp32 (128 KB), swizzle col ^ (row & 31)
    float* stage = (float*)sm;
    __syncthreads();
#pragma unroll
    for (int mt = 0; mt < 4; mt++) {
#pragma unroll
        for (int h = 0; h < 2; h++) {
            const int rl = wm * 64 + mt * 16 + qrow + h * 8;
#pragma unroll
            for (int n8 = 0; n8 < 8; n8++) {
                const int cl = wn * 64 + n8 * 8 + qcol;
                float v0 = acc[mt][n8][h * 2 + 0];
                float v1 = acc[mt][n8][h * 2 + 1];
                const size_t ao = (size_t)(bM + rl) * LD + bN + cl;
                __nv_bfloat162 a2 = *(const __nv_bfloat162*)(auxhi + ao);
                __nv_bfloat162 l2 = *(const __nv_bfloat162*)(auxlo + ao);
                v0 = fmaf(NSC_A, __bfloat162float(a2.x) + __bfloat162float(l2.x), v0);
                v1 = fmaf(NSC_A, __bfloat162float(a2.y) + __bfloat162float(l2.y), v1);
                stage[rl * 256 + (cl ^ (rl & 31))] = v0;
                stage[rl * 256 + ((cl + 1) ^ (rl & 31))] = v1;
            }
        }
    }
    __syncthreads();

    // normal orientation: warp w rows w*16..+15; lane covers col pairs 2l + 64j
    {
        const int cb = lane * 2;
#pragma unroll 2
        for (int rr = 0; rr < 16; rr++) {
            const int r = wid * 16 + rr;
            const int rx = r & 31;
#pragma unroll
            for (int j = 0; j < 4; j++) {
                const int c = cb + 64 * j;
                float f0 = stage[r * 256 + (c ^ rx)];
                float f1 = stage[r * 256 + ((c + 1) ^ rx)];
                store_split2(Chi, Clo, (size_t)(bM + r) * LD + bN + c, f0, f1);
            }
        }
    }
    // transposed orientation: out rows r' = w*32..+31 (256 total), col pairs 2l + 64j (128)
    {
        const int cb = lane * 2;
#pragma unroll 2
        for (int rr = 0; rr < 32; rr++) {
            const int rp = wid * 32 + rr;  // 0..255
#pragma unroll
            for (int j = 0; j < 2; j++) {
                const int cp = cb + 64 * j;  // 0..127
                float f0 = stage[cp * 256 + (rp ^ (cp & 31))];
                float f1 = stage[(cp + 1) * 256 + (rp ^ ((cp + 1) & 31))];
                store_split2(Thi, Tlo, (size_t)(bN + rp) * LD + bM + cp, f0, f1);
            }
        }
    }
}

// ---------------- launch -----------------------------------------------------
extern "C" void kernel_launch(void* const* d_in, const int* in_sizes, int n_in,
                              void* d_out, int out_size) {
    const float* x = nullptr;
    const float* w = nullptr;
    const float* bias = nullptr;
    int x_size = 0;
    for (int i = 0; i < n_in; i++) {
        const int sz = in_sizes[i];
        if (sz == DIM) bias = (const float*)d_in[i];
        else if (sz == DIM * DIM) w = (const float*)d_in[i];
        else { x = (const float*)d_in[i]; x_size = sz; }
    }
    const int B_rows = x_size / DIM;  // 16384
    float* out = (float*)d_out;

    float* pX;
    __nv_bfloat16 *pXhi[2], *pXlo[2], *pXThi[2], *pXTlo[2];
    __nv_bfloat16 *pGhi, *pGlo, *pBhi, *pBlo, *pxh, *pxl;
    cudaGetSymbolAddress((void**)&pX, g_X);
    {
        __nv_bfloat16* base;
        cudaGetSymbolAddress((void**)&base, g_Xhi);
        pXhi[0] = base; pXhi[1] = base + DIM * DIM;
        cudaGetSymbolAddress((void**)&base, g_Xlo);
        pXlo[0] = base; pXlo[1] = base + DIM * DIM;
        cudaGetSymbolAddress((void**)&base, g_XThi);
        pXThi[0] = base; pXThi[1] = base + DIM * DIM;
        cudaGetSymbolAddress((void**)&base, g_XTlo);
        pXTlo[0] = base; pXTlo[1] = base + DIM * DIM;
    }
    cudaGetSymbolAddress((void**)&pGhi, g_Ghi);
    cudaGetSymbolAddress((void**)&pGlo, g_Glo);
    cudaGetSymbolAddress((void**)&pBhi, g_Bhi);
    cudaGetSymbolAddress((void**)&pBlo, g_Blo);
    cudaGetSymbolAddress((void**)&pxh, g_xbig_hi);
    cudaGetSymbolAddress((void**)&pxl, g_xbig_lo);

    cudaFuncSetAttribute(mmagemm<0>, cudaFuncAttributeMaxDynamicSharedMemorySize, SMEM_TOTAL);
    cudaFuncSetAttribute(mmagemm<1>, cudaFuncAttributeMaxDynamicSharedMemorySize, SMEM_TOTAL);
    cudaFuncSetAttribute(mmagemm_big<2>, cudaFuncAttributeMaxDynamicSharedMemorySize, SMEM_BIG);
    cudaFuncSetAttribute(mmagemm_big<3>, cudaFuncAttributeMaxDynamicSharedMemorySize, SMEM_BIG);

    const int n = DIM * DIM;
    norm_partial_kernel<<<256, 256>>>(w, n);
    norm_finalize_kernel<<<1, 256>>>();
    scale_split_kernel<<<1024, 256>>>(w, pX, pXhi[0], pXlo[0], n);
    strans_kernel<<<dim3(64, 64), dim3(32, 8)>>>(pX, pXThi[0], pXTlo[0]);
    split_kernel<<<8192, 256>>>(x, pxh, pxl, B_rows * DIM);

    dim3 blk(256);
    const int NT = DIM / BM;                 // 16
    dim3 gtri(NT * (NT + 1) / 2, 1);         // 136 CTAs
    dim3 g2(DIM / B2N, DIM / B2M);           // (8, 16) = 128 CTAs
    for (int s = 0; s < 10; s++) {
        const int c0 = s & 1, n1 = c0 ^ 1;
        // G = X @ X^T (symmetric, triangular + mirror)
        mmagemm<0><<<gtri, blk, SMEM_TOTAL>>>(
            pXhi[c0], pXlo[c0], pXhi[c0], pXlo[c0],
            nullptr, nullptr, pGhi, pGlo);
        // Bm = c*(G@G) + b*G (symmetric, triangular + mirror)
        mmagemm<1><<<gtri, blk, SMEM_TOTAL>>>(
            pGhi, pGlo, pGhi, pGlo,
            pGhi, pGlo, pBhi, pBlo);
        // X' = Bm@X + a*X ; writes X'[n1] split + X'^T[n1] split
        mmagemm_big<2><<<g2, blk, SMEM_BIG>>>(
            pBhi, pBlo, pXThi[c0], pXTlo[c0],
            pXhi[c0], pXlo[c0], nullptr,
            pXhi[n1], pXlo[n1], pXThi[n1], pXTlo[n1], nullptr);
    }
    // out = x @ Xfinal + bias
    dim3 gout(DIM / B2N, B_rows / B2M);  // (8, 128)
    mmagemm_big<3><<<gout, blk, SMEM_BIG>>>(
        pxh, pxl, pXThi[0], pXTlo[0],
        nullptr, nullptr, bias, nullptr, nullptr, nullptr, nullptr, out);
}